// round 1
// baseline (speedup 1.0000x reference)
#include <cuda_runtime.h>
#include <cuda_bf16.h>

// Problem constants
#define BB    8
#define NN    4096
#define WROW  128          // 4096/32 bitmask words per row
#define ROWS  (BB*NN)      // 32768
#define INDIM 16420
#define HID   128
#define NACT  16
#define CK    514          // fc1 split-K chunk (32*514 >= 16420)

// ---------------- scratch (static __device__, no allocations) ----------------
__device__ unsigned g_bits[(size_t)ROWS * WROW];   // 16 MB packed adjacency (with self loops)
__device__ float    g_dinv[ROWS];
__device__ float4   g_v [ROWS];                    // dinv * (x @ W1)
__device__ float4   g_v2[ROWS];                    // dinv * (h @ W2)
__device__ float4   g_pa[2 * ROWS];                // layer1 partial sums (j halves)
__device__ float4   g_pb[2 * ROWS];                // layer2 partial sums
__device__ float    g_zacc[BB * HID];

// ---------------- K1: adj -> bitmask + dinv ----------------
// one block per row; 256 threads; int4 coalesced reads; ballot-free packing via shfl-OR
__global__ void __launch_bounds__(256) prep_kernel(const int* __restrict__ adj)
{
    int row = blockIdx.x;                 // 0..32767
    int i   = row & (NN - 1);
    int t   = threadIdx.x;
    int lane = t & 31;

    const int4* arow = (const int4*)(adj + ((size_t)row << 12));
    unsigned*   brow = g_bits + ((size_t)row << 7);

    unsigned cnt = 0;
#pragma unroll
    for (int it = 0; it < 4; ++it) {
        int j0 = it * 1024 + t * 4;
        int4 v = arow[it * 256 + t];
        unsigned nib = (unsigned)((v.x != 0) | ((v.y != 0) << 1) |
                                  ((v.z != 0) << 2) | ((v.w != 0) << 3));
        unsigned dio = (unsigned)(i - j0);
        if (dio < 4u) nib |= 1u << dio;   // force self-loop (A = max(A, I))
        unsigned w = nib << ((lane & 7) * 4);
        w |= __shfl_xor_sync(0xffffffffu, w, 1);
        w |= __shfl_xor_sync(0xffffffffu, w, 2);
        w |= __shfl_xor_sync(0xffffffffu, w, 4);
        if ((lane & 7) == 0) {
            brow[j0 >> 5] = w;
            cnt += __popc(w);
        }
    }
    // block reduce degree
    cnt += __shfl_down_sync(0xffffffffu, cnt, 16);
    cnt += __shfl_down_sync(0xffffffffu, cnt, 8);
    cnt += __shfl_down_sync(0xffffffffu, cnt, 4);
    cnt += __shfl_down_sync(0xffffffffu, cnt, 2);
    cnt += __shfl_down_sync(0xffffffffu, cnt, 1);
    __shared__ unsigned scnt[8];
    if (lane == 0) scnt[t >> 5] = cnt;
    __syncthreads();
    if (t == 0) {
        unsigned deg = 0;
#pragma unroll
        for (int w = 0; w < 8; ++w) deg += scnt[w];
        g_dinv[row] = rsqrtf((float)deg);
    }
}

// ---------------- K2: v = dinv * (x @ W1) ----------------
__global__ void v1_kernel(const float* __restrict__ x, const float* __restrict__ W1)
{
    int id = blockIdx.x * blockDim.x + threadIdx.x;
    if (id >= ROWS) return;
    float x0 = x[id*3], x1 = x[id*3+1], x2 = x[id*3+2];
    float d = g_dinv[id];
    float u0 = x0*W1[0] + x1*W1[3] + x2*W1[6];
    float u1 = x0*W1[1] + x1*W1[4] + x2*W1[7];
    float u2 = x0*W1[2] + x1*W1[5] + x2*W1[8];
    g_v[id] = make_float4(d*u0, d*u1, d*u2, 0.f);
}

// ---------------- zacc init ----------------
__global__ void zinit_kernel(const float* __restrict__ fcb1)
{
    g_zacc[blockIdx.x * HID + threadIdx.x] = fcb1[threadIdx.x];
}

// ---------------- K3/K5: masked aggregation  part[half] = A_half @ v ----------------
// 128 threads, thread t owns row (row0+t). 512 blocks: (b, tile, j-half).
// Bits staged in smem with stride 33 (bank = (t+k)%32, conflict free);
// v chunk staged as float4, inner read is uniform broadcast LDS.128.
template<int L>
__global__ void __launch_bounds__(128) agg_kernel()
{
    __shared__ unsigned sb[128 * 33];
    __shared__ float4   sv[1024];

    const float4* vin = (L == 0) ? g_v  : g_v2;
    float4*       part = (L == 0) ? g_pa : g_pb;

    int bx   = blockIdx.x;
    int b    = bx >> 6;
    int tile = (bx >> 1) & 31;
    int half = bx & 1;
    int row0 = tile * 128;
    int t    = threadIdx.x;

    const unsigned* gb = g_bits + ((size_t)(b * NN + row0)) * WROW + half * 64;
    const float4*   gv = vin + b * NN + half * 2048;

    float ax0=0,ax1=0,ax2=0,ax3=0;
    float ay0=0,ay1=0,ay2=0,ay3=0;
    float az0=0,az1=0,az2=0,az3=0;

    for (int c = 0; c < 2; ++c) {
        __syncthreads();
#pragma unroll
        for (int q = 0; q < 8; ++q)
            sv[q * 128 + t] = gv[c * 1024 + q * 128 + t];
#pragma unroll
        for (int q = 0; q < 32; ++q) {
            int idx = q * 128 + t;
            int r = idx >> 5, w = idx & 31;
            sb[r * 33 + w] = gb[(size_t)r * WROW + c * 32 + w];
        }
        __syncthreads();

        for (int k = 0; k < 32; ++k) {
            unsigned wb = sb[t * 33 + k];
            const float4* vp = &sv[k * 32];
#pragma unroll
            for (int u = 0; u < 32; u += 4) {
                {
                    float m = (float)((wb >> (u+0)) & 1u);
                    float4 vv = vp[u+0];
                    ax0 = fmaf(m, vv.x, ax0); ay0 = fmaf(m, vv.y, ay0); az0 = fmaf(m, vv.z, az0);
                }
                {
                    float m = (float)((wb >> (u+1)) & 1u);
                    float4 vv = vp[u+1];
                    ax1 = fmaf(m, vv.x, ax1); ay1 = fmaf(m, vv.y, ay1); az1 = fmaf(m, vv.z, az1);
                }
                {
                    float m = (float)((wb >> (u+2)) & 1u);
                    float4 vv = vp[u+2];
                    ax2 = fmaf(m, vv.x, ax2); ay2 = fmaf(m, vv.y, ay2); az2 = fmaf(m, vv.z, az2);
                }
                {
                    float m = (float)((wb >> (u+3)) & 1u);
                    float4 vv = vp[u+3];
                    ax3 = fmaf(m, vv.x, ax3); ay3 = fmaf(m, vv.y, ay3); az3 = fmaf(m, vv.z, az3);
                }
            }
        }
    }
    float sx = (ax0+ax1)+(ax2+ax3);
    float sy = (ay0+ay1)+(ay2+ay3);
    float sz = (az0+az1)+(az2+az3);
    part[half * ROWS + b * NN + row0 + t] = make_float4(sx, sy, sz, 0.f);
}

// ---------------- K4: combine layer1 partials, relu, v2 = dinv * (h @ W2) ----------------
__global__ void v2_kernel(const float* __restrict__ W2, const float* __restrict__ b1)
{
    int id = blockIdx.x * blockDim.x + threadIdx.x;
    if (id >= ROWS) return;
    float4 p0 = g_pa[id];
    float4 p1 = g_pa[ROWS + id];
    float d = g_dinv[id];
    float h0 = fmaxf(d * (p0.x + p1.x) + b1[0], 0.f);
    float h1 = fmaxf(d * (p0.y + p1.y) + b1[1], 0.f);
    float h2 = fmaxf(d * (p0.z + p1.z) + b1[2], 0.f);
    float u0 = h0*W2[0] + h1*W2[3] + h2*W2[6];
    float u1 = h0*W2[1] + h1*W2[4] + h2*W2[7];
    float u2 = h0*W2[2] + h1*W2[5] + h2*W2[8];
    g_v2[id] = make_float4(d*u0, d*u1, d*u2, 0.f);
}

// ---------------- K6: fc1 split-K, z built on the fly, atomic accumulate ----------------
__global__ void __launch_bounds__(128) fc1_kernel(
    const float* __restrict__ idxin, const float* __restrict__ y,
    const float* __restrict__ b2, const float* __restrict__ fcW1)
{
    __shared__ float zc[CK];
    int bx = blockIdx.x;
    int b  = bx >> 5;
    int s  = bx & 31;
    int k0 = s * CK;
    int klen = min(CK, INDIM - k0);
    int t = threadIdx.x;

    for (int kk = t; kk < klen; kk += 128) {
        int k = k0 + kk;
        float z;
        if (k < NN) {
            z = idxin[b * NN + k];
        } else if (k < NN + 3 * NN) {
            int g = k - NN;
            int i = g / 3;
            int f = g - i * 3;
            const float* p0 = (const float*)&g_pb[b * NN + i];
            const float* p1 = (const float*)&g_pb[ROWS + b * NN + i];
            z = g_dinv[b * NN + i] * (p0[f] + p1[f]) + b2[f];
        } else {
            z = y[b * 36 + (k - (NN + 3 * NN))];
        }
        zc[kk] = z;
    }
    __syncthreads();

    float acc = 0.f;
    const float* wcol = fcW1 + (size_t)k0 * HID + t;
    int kk = 0;
    for (; kk + 4 <= klen; kk += 4) {
        acc += zc[kk+0] * wcol[(size_t)(kk+0) * HID];
        acc += zc[kk+1] * wcol[(size_t)(kk+1) * HID];
        acc += zc[kk+2] * wcol[(size_t)(kk+2) * HID];
        acc += zc[kk+3] * wcol[(size_t)(kk+3) * HID];
    }
    for (; kk < klen; ++kk)
        acc += zc[kk] * wcol[(size_t)kk * HID];

    atomicAdd(&g_zacc[b * HID + t], acc);
}

// ---------------- K7: relu + fc2 ----------------
__global__ void __launch_bounds__(128) fin_kernel(
    const float* __restrict__ fcW2, const float* __restrict__ fcb2, float* __restrict__ out)
{
    __shared__ float sm[HID];
    int b = blockIdx.x, t = threadIdx.x;
    sm[t] = fmaxf(g_zacc[b * HID + t], 0.f);
    __syncthreads();
    if (t < NACT) {
        float o = fcb2[t];
#pragma unroll 8
        for (int h = 0; h < HID; ++h)
            o += sm[h] * fcW2[h * NACT + t];
        out[b * NACT + t] = o;
    }
}

// ---------------- launch ----------------
extern "C" void kernel_launch(void* const* d_in, const int* in_sizes, int n_in,
                              void* d_out, int out_size)
{
    const float* idxin = (const float*)d_in[0];   // [8,4096]
    const float* x     = (const float*)d_in[1];   // [8,4096,3]
    const float* y     = (const float*)d_in[2];   // [8,12,3]
    const int*   adj   = (const int*)  d_in[3];   // [8,4096,4096]
    const float* W1    = (const float*)d_in[4];
    const float* b1    = (const float*)d_in[5];
    const float* W2    = (const float*)d_in[6];
    const float* b2    = (const float*)d_in[7];
    const float* fcW1  = (const float*)d_in[8];
    const float* fcb1  = (const float*)d_in[9];
    const float* fcW2  = (const float*)d_in[10];
    const float* fcb2  = (const float*)d_in[11];
    float* out = (float*)d_out;

    prep_kernel<<<ROWS, 256>>>(adj);
    zinit_kernel<<<BB, HID>>>(fcb1);
    v1_kernel<<<ROWS / 256, 256>>>(x, W1);
    agg_kernel<0><<<512, 128>>>();
    v2_kernel<<<ROWS / 256, 256>>>(W2, b1);
    agg_kernel<1><<<512, 128>>>();
    fc1_kernel<<<BB * 32, 128>>>(idxin, y, b2, fcW1);
    fin_kernel<<<BB, 128>>>(fcW2, fcb2, out);
}

// round 2
// speedup vs baseline: 1.0354x; 1.0354x over previous
#include <cuda_runtime.h>
#include <cuda_bf16.h>

// Problem constants
#define BB    8
#define NN    4096
#define WROW  128          // 4096/32 bitmask words per row
#define ROWS  (BB*NN)      // 32768
#define INDIM 16420
#define HID   128
#define NACT  16
#define CK    514          // fc1 split-K chunk (32*514 >= 16420)

// ---------------- scratch (static __device__, no allocations) ----------------
__device__ unsigned g_bits[(size_t)ROWS * WROW];   // 16 MB packed adjacency (with self loops)
__device__ float    g_dinv[ROWS];
__device__ float4   g_v [ROWS];                    // dinv * (x @ W1)
__device__ float4   g_v2[ROWS];                    // dinv * (h @ W2)
__device__ float4   g_pa[2 * ROWS];                // layer1 partial sums (j halves)
__device__ float4   g_pb[2 * ROWS];                // layer2 partial sums
__device__ float    g_zacc[BB * HID];

// ---------------- K1: adj -> bitmask + dinv ----------------
// one block per row; 256 threads; int4 coalesced reads; ballot-free packing via shfl-OR
__global__ void __launch_bounds__(256) prep_kernel(const int* __restrict__ adj)
{
    int row = blockIdx.x;                 // 0..32767
    int i   = row & (NN - 1);
    int t   = threadIdx.x;
    int lane = t & 31;

    const int4* arow = (const int4*)(adj + ((size_t)row << 12));
    unsigned*   brow = g_bits + ((size_t)row << 7);

    unsigned cnt = 0;
#pragma unroll
    for (int it = 0; it < 4; ++it) {
        int j0 = it * 1024 + t * 4;
        int4 v = arow[it * 256 + t];
        unsigned nib = (unsigned)((v.x != 0) | ((v.y != 0) << 1) |
                                  ((v.z != 0) << 2) | ((v.w != 0) << 3));
        unsigned dio = (unsigned)(i - j0);
        if (dio < 4u) nib |= 1u << dio;   // force self-loop (A = max(A, I))
        unsigned w = nib << ((lane & 7) * 4);
        w |= __shfl_xor_sync(0xffffffffu, w, 1);
        w |= __shfl_xor_sync(0xffffffffu, w, 2);
        w |= __shfl_xor_sync(0xffffffffu, w, 4);
        if ((lane & 7) == 0) {
            brow[j0 >> 5] = w;
            cnt += __popc(w);
        }
    }
    // block reduce degree
    cnt += __shfl_down_sync(0xffffffffu, cnt, 16);
    cnt += __shfl_down_sync(0xffffffffu, cnt, 8);
    cnt += __shfl_down_sync(0xffffffffu, cnt, 4);
    cnt += __shfl_down_sync(0xffffffffu, cnt, 2);
    cnt += __shfl_down_sync(0xffffffffu, cnt, 1);
    __shared__ unsigned scnt[8];
    if (lane == 0) scnt[t >> 5] = cnt;
    __syncthreads();
    if (t == 0) {
        unsigned deg = 0;
#pragma unroll
        for (int w = 0; w < 8; ++w) deg += scnt[w];
        g_dinv[row] = rsqrtf((float)deg);
    }
}

// ---------------- K2: v = dinv * (x @ W1) ----------------
__global__ void v1_kernel(const float* __restrict__ x, const float* __restrict__ W1)
{
    int id = blockIdx.x * blockDim.x + threadIdx.x;
    if (id >= ROWS) return;
    float x0 = x[id*3], x1 = x[id*3+1], x2 = x[id*3+2];
    float d = g_dinv[id];
    float u0 = x0*W1[0] + x1*W1[3] + x2*W1[6];
    float u1 = x0*W1[1] + x1*W1[4] + x2*W1[7];
    float u2 = x0*W1[2] + x1*W1[5] + x2*W1[8];
    g_v[id] = make_float4(d*u0, d*u1, d*u2, 0.f);
}

// ---------------- zacc init ----------------
__global__ void zinit_kernel(const float* __restrict__ fcb1)
{
    g_zacc[blockIdx.x * HID + threadIdx.x] = fcb1[threadIdx.x];
}

// ---------------- K3/K5: masked aggregation  part[half] = A_half @ v ----------------
// 128 threads, thread t owns row (row0+t). 512 blocks: (b, tile, j-half).
// Bits staged in smem with stride 33 (bank = (t+k)%32, conflict free);
// v chunk staged as float4, inner read is uniform broadcast LDS.128.
template<int L>
__global__ void __launch_bounds__(128) agg_kernel()
{
    __shared__ unsigned sb[128 * 33];
    __shared__ float4   sv[1024];

    const float4* vin = (L == 0) ? g_v  : g_v2;
    float4*       part = (L == 0) ? g_pa : g_pb;

    int bx   = blockIdx.x;
    int b    = bx >> 6;
    int tile = (bx >> 1) & 31;
    int half = bx & 1;
    int row0 = tile * 128;
    int t    = threadIdx.x;

    const unsigned* gb = g_bits + ((size_t)(b * NN + row0)) * WROW + half * 64;
    const float4*   gv = vin + b * NN + half * 2048;

    float ax0=0,ax1=0,ax2=0,ax3=0;
    float ay0=0,ay1=0,ay2=0,ay3=0;
    float az0=0,az1=0,az2=0,az3=0;

    for (int c = 0; c < 2; ++c) {
        __syncthreads();
#pragma unroll
        for (int q = 0; q < 8; ++q)
            sv[q * 128 + t] = gv[c * 1024 + q * 128 + t];
#pragma unroll
        for (int q = 0; q < 32; ++q) {
            int idx = q * 128 + t;
            int r = idx >> 5, w = idx & 31;
            sb[r * 33 + w] = gb[(size_t)r * WROW + c * 32 + w];
        }
        __syncthreads();

        for (int k = 0; k < 32; ++k) {
            unsigned wb = sb[t * 33 + k];
            const float4* vp = &sv[k * 32];
#pragma unroll
            for (int u = 0; u < 32; u += 4) {
                {
                    float m = (float)((wb >> (u+0)) & 1u);
                    float4 vv = vp[u+0];
                    ax0 = fmaf(m, vv.x, ax0); ay0 = fmaf(m, vv.y, ay0); az0 = fmaf(m, vv.z, az0);
                }
                {
                    float m = (float)((wb >> (u+1)) & 1u);
                    float4 vv = vp[u+1];
                    ax1 = fmaf(m, vv.x, ax1); ay1 = fmaf(m, vv.y, ay1); az1 = fmaf(m, vv.z, az1);
                }
                {
                    float m = (float)((wb >> (u+2)) & 1u);
                    float4 vv = vp[u+2];
                    ax2 = fmaf(m, vv.x, ax2); ay2 = fmaf(m, vv.y, ay2); az2 = fmaf(m, vv.z, az2);
                }
                {
                    float m = (float)((wb >> (u+3)) & 1u);
                    float4 vv = vp[u+3];
                    ax3 = fmaf(m, vv.x, ax3); ay3 = fmaf(m, vv.y, ay3); az3 = fmaf(m, vv.z, az3);
                }
            }
        }
    }
    float sx = (ax0+ax1)+(ax2+ax3);
    float sy = (ay0+ay1)+(ay2+ay3);
    float sz = (az0+az1)+(az2+az3);
    part[half * ROWS + b * NN + row0 + t] = make_float4(sx, sy, sz, 0.f);
}

// ---------------- K4: combine layer1 partials, relu, v2 = dinv * (h @ W2) ----------------
__global__ void v2_kernel(const float* __restrict__ W2, const float* __restrict__ b1)
{
    int id = blockIdx.x * blockDim.x + threadIdx.x;
    if (id >= ROWS) return;
    float4 p0 = g_pa[id];
    float4 p1 = g_pa[ROWS + id];
    float d = g_dinv[id];
    float h0 = fmaxf(d * (p0.x + p1.x) + b1[0], 0.f);
    float h1 = fmaxf(d * (p0.y + p1.y) + b1[1], 0.f);
    float h2 = fmaxf(d * (p0.z + p1.z) + b1[2], 0.f);
    float u0 = h0*W2[0] + h1*W2[3] + h2*W2[6];
    float u1 = h0*W2[1] + h1*W2[4] + h2*W2[7];
    float u2 = h0*W2[2] + h1*W2[5] + h2*W2[8];
    g_v2[id] = make_float4(d*u0, d*u1, d*u2, 0.f);
}

// ---------------- K6: fc1 split-K, z built on the fly, atomic accumulate ----------------
__global__ void __launch_bounds__(128) fc1_kernel(
    const float* __restrict__ idxin, const float* __restrict__ y,
    const float* __restrict__ b2, const float* __restrict__ fcW1)
{
    __shared__ float zc[CK];
    int bx = blockIdx.x;
    int b  = bx >> 5;
    int s  = bx & 31;
    int k0 = s * CK;
    int klen = min(CK, INDIM - k0);
    int t = threadIdx.x;

    for (int kk = t; kk < klen; kk += 128) {
        int k = k0 + kk;
        float z;
        if (k < NN) {
            z = idxin[b * NN + k];
        } else if (k < NN + 3 * NN) {
            int g = k - NN;
            int i = g / 3;
            int f = g - i * 3;
            const float* p0 = (const float*)&g_pb[b * NN + i];
            const float* p1 = (const float*)&g_pb[ROWS + b * NN + i];
            z = g_dinv[b * NN + i] * (p0[f] + p1[f]) + b2[f];
        } else {
            z = y[b * 36 + (k - (NN + 3 * NN))];
        }
        zc[kk] = z;
    }
    __syncthreads();

    float acc = 0.f;
    const float* wcol = fcW1 + (size_t)k0 * HID + t;
    int kk = 0;
    for (; kk + 4 <= klen; kk += 4) {
        acc += zc[kk+0] * wcol[(size_t)(kk+0) * HID];
        acc += zc[kk+1] * wcol[(size_t)(kk+1) * HID];
        acc += zc[kk+2] * wcol[(size_t)(kk+2) * HID];
        acc += zc[kk+3] * wcol[(size_t)(kk+3) * HID];
    }
    for (; kk < klen; ++kk)
        acc += zc[kk] * wcol[(size_t)kk * HID];

    atomicAdd(&g_zacc[b * HID + t], acc);
}

// ---------------- K7: relu + fc2 ----------------
__global__ void __launch_bounds__(128) fin_kernel(
    const float* __restrict__ fcW2, const float* __restrict__ fcb2, float* __restrict__ out)
{
    __shared__ float sm[HID];
    int b = blockIdx.x, t = threadIdx.x;
    sm[t] = fmaxf(g_zacc[b * HID + t], 0.f);
    __syncthreads();
    if (t < NACT) {
        float o = fcb2[t];
#pragma unroll 8
        for (int h = 0; h < HID; ++h)
            o += sm[h] * fcW2[h * NACT + t];
        out[b * NACT + t] = o;
    }
}

// ---------------- launch ----------------
extern "C" void kernel_launch(void* const* d_in, const int* in_sizes, int n_in,
                              void* d_out, int out_size)
{
    const float* idxin = (const float*)d_in[0];   // [8,4096]
    const float* x     = (const float*)d_in[1];   // [8,4096,3]
    const float* y     = (const float*)d_in[2];   // [8,12,3]
    const int*   adj   = (const int*)  d_in[3];   // [8,4096,4096]
    const float* W1    = (const float*)d_in[4];
    const float* b1    = (const float*)d_in[5];
    const float* W2    = (const float*)d_in[6];
    const float* b2    = (const float*)d_in[7];
    const float* fcW1  = (const float*)d_in[8];
    const float* fcb1  = (const float*)d_in[9];
    const float* fcW2  = (const float*)d_in[10];
    const float* fcb2  = (const float*)d_in[11];
    float* out = (float*)d_out;

    prep_kernel<<<ROWS, 256>>>(adj);
    zinit_kernel<<<BB, HID>>>(fcb1);
    v1_kernel<<<ROWS / 256, 256>>>(x, W1);
    agg_kernel<0><<<512, 128>>>();
    v2_kernel<<<ROWS / 256, 256>>>(W2, b1);
    agg_kernel<1><<<512, 128>>>();
    fc1_kernel<<<BB * 32, 128>>>(idxin, y, b2, fcW1);
    fin_kernel<<<BB, 128>>>(fcW2, fcb2, out);
}

// round 4
// speedup vs baseline: 1.1468x; 1.1076x over previous
#include <cuda_runtime.h>
#include <cuda_bf16.h>

// Problem constants
#define BB    8
#define NN    4096
#define WROW  128          // 4096/32 bitmask words per row
#define ROWS  (BB*NN)      // 32768
#define INDIM 16420
#define HID   128
#define NACT  16
#define CK    514          // fc1 split-K chunk (32*514 >= 16420)
#define NQ    4            // column quarters per row in agg

// ---------------- scratch (static __device__, no allocations) ----------------
__device__ unsigned g_bits[(size_t)ROWS * WROW];   // 16 MB packed adjacency (with self loops)
__device__ float    g_dinv[ROWS];
__device__ float4   g_v [ROWS];                    // dinv * (x @ W1)
__device__ float4   g_v2[ROWS];                    // dinv * (h @ W2)
__device__ float4   g_pa[NQ * ROWS];               // layer1 partial sums (col quarters)
__device__ float4   g_pb[NQ * ROWS];               // layer2 partial sums
__device__ float    g_zacc[BB * HID];

// ---------------- K1: adj -> bitmask + dinv + v1 + zacc init ----------------
__global__ void __launch_bounds__(256) prep_kernel(
    const int* __restrict__ adj, const float* __restrict__ x,
    const float* __restrict__ W1, const float* __restrict__ fcb1)
{
    int row = blockIdx.x;                 // 0..32767
    int i   = row & (NN - 1);
    int t   = threadIdx.x;
    int lane = t & 31;

    // fused zacc init (first 8 blocks)
    if (row < BB && t < HID) g_zacc[row * HID + t] = fcb1[t];

    const int4* arow = (const int4*)(adj + ((size_t)row << 12));
    unsigned*   brow = g_bits + ((size_t)row << 7);

    unsigned cnt = 0;
#pragma unroll
    for (int it = 0; it < 4; ++it) {
        int j0 = it * 1024 + t * 4;
        int4 v = arow[it * 256 + t];
        unsigned nib = (unsigned)((v.x != 0) | ((v.y != 0) << 1) |
                                  ((v.z != 0) << 2) | ((v.w != 0) << 3));
        unsigned dio = (unsigned)(i - j0);
        if (dio < 4u) nib |= 1u << dio;   // force self-loop (A = max(A, I))
        unsigned w = nib << ((lane & 7) * 4);
        w |= __shfl_xor_sync(0xffffffffu, w, 1);
        w |= __shfl_xor_sync(0xffffffffu, w, 2);
        w |= __shfl_xor_sync(0xffffffffu, w, 4);
        if ((lane & 7) == 0) {
            brow[j0 >> 5] = w;
            cnt += __popc(w);
        }
    }
    // block reduce degree
    cnt += __shfl_down_sync(0xffffffffu, cnt, 16);
    cnt += __shfl_down_sync(0xffffffffu, cnt, 8);
    cnt += __shfl_down_sync(0xffffffffu, cnt, 4);
    cnt += __shfl_down_sync(0xffffffffu, cnt, 2);
    cnt += __shfl_down_sync(0xffffffffu, cnt, 1);
    __shared__ unsigned scnt[8];
    if (lane == 0) scnt[t >> 5] = cnt;
    __syncthreads();
    if (t == 0) {
        unsigned deg = 0;
#pragma unroll
        for (int w = 0; w < 8; ++w) deg += scnt[w];
        float d = rsqrtf((float)deg);
        g_dinv[row] = d;
        // fused v1: v = dinv * (x @ W1)
        float x0 = x[row*3], x1 = x[row*3+1], x2 = x[row*3+2];
        float u0 = x0*W1[0] + x1*W1[3] + x2*W1[6];
        float u1 = x0*W1[1] + x1*W1[4] + x2*W1[7];
        float u2 = x0*W1[2] + x1*W1[5] + x2*W1[8];
        g_v[row] = make_float4(d*u0, d*u1, d*u2, 0.f);
    }
}

// ---------------- masked aggregation with predicated packed adds ----------------
// Per column: bit-test predicate + @p add.rn.f32x2 (x,y) + @p add.f32 (z),
// v fetched via broadcast ld.shared.v2.b64. All offsets/bit-masks are
// register operands that ptxas constant-folds into immediate forms after unroll.

#define COLACC(AXY, AZ, WB, BIT, VXY, VZ)                          \
    asm volatile("{\n\t"                                           \
        ".reg .pred p;\n\t"                                        \
        ".reg .b32 r;\n\t"                                         \
        "and.b32 r, %2, %3;\n\t"                                   \
        "setp.ne.b32 p, r, 0;\n\t"                                 \
        "@p add.rn.f32x2 %0, %0, %4;\n\t"                          \
        "@p add.f32 %1, %1, %5;\n\t"                               \
        "}"                                                        \
        : "+l"(AXY), "+f"(AZ)                                      \
        : "r"(WB), "r"(BIT), "l"(VXY), "f"(VZ))

__device__ __forceinline__ void acc_word(
    unsigned wb, unsigned cb,
    unsigned long long& a0xy, float& a0z,
    unsigned long long& a1xy, float& a1z)
{
#pragma unroll
    for (int u = 0; u < 32; u += 2) {
        unsigned long long vxy0, vzw0, vxy1, vzw1;
        float vz0, vz1;
        asm volatile("ld.shared.v2.b64 {%0, %1}, [%2];"
                     : "=l"(vxy0), "=l"(vzw0) : "r"(cb + u * 16));
        asm volatile("ld.shared.v2.b64 {%0, %1}, [%2];"
                     : "=l"(vxy1), "=l"(vzw1) : "r"(cb + (u + 1) * 16));
        asm volatile("{ .reg .b32 hi; mov.b64 {%0, hi}, %1; }" : "=f"(vz0) : "l"(vzw0));
        asm volatile("{ .reg .b32 hi; mov.b64 {%0, hi}, %1; }" : "=f"(vz1) : "l"(vzw1));
        COLACC(a0xy, a0z, wb, 1u << u,       vxy0, vz0);
        COLACC(a1xy, a1z, wb, 1u << (u + 1), vxy1, vz1);
    }
}

// grid = 1024 blocks: (b in 8) x (tile in 32) x (quarter in 4); 128 threads = 128 rows
template<int L>
__global__ void __launch_bounds__(128) agg_kernel()
{
    __shared__ float4 sv[1024];

    const float4* vin  = (L == 0) ? g_v  : g_v2;
    float4*       part = (L == 0) ? g_pa : g_pb;

    int bx   = blockIdx.x;
    int b    = bx >> 7;
    int tile = (bx >> 2) & 31;
    int q    = bx & 3;
    int t    = threadIdx.x;
    int row  = b * NN + tile * 128 + t;

    // bits for this row's quarter: 32 words = 8 uint4, software pipelined
    const uint4* gw = (const uint4*)(g_bits + (size_t)row * WROW + q * 32);
    uint4 wcur = gw[0];

    // stage v chunk (1024 cols) for broadcast reads
    const float4* gv = vin + b * NN + q * 1024;
#pragma unroll
    for (int i = 0; i < 8; ++i)
        sv[i * 128 + t] = gv[i * 128 + t];
    __syncthreads();

    unsigned sva = (unsigned)__cvta_generic_to_shared(sv);

    unsigned long long a0xy = 0ull, a1xy = 0ull;
    float a0z = 0.f, a1z = 0.f;

#pragma unroll 1
    for (int g = 0; g < 8; ++g) {
        uint4 wnext = wcur;
        if (g < 7) wnext = gw[g + 1];
        unsigned cb = sva + (unsigned)g * 2048;
        acc_word(wcur.x, cb,        a0xy, a0z, a1xy, a1z);
        acc_word(wcur.y, cb + 512,  a0xy, a0z, a1xy, a1z);
        acc_word(wcur.z, cb + 1024, a0xy, a0z, a1xy, a1z);
        acc_word(wcur.w, cb + 1536, a0xy, a0z, a1xy, a1z);
        wcur = wnext;
    }

    unsigned long long axy;
    asm volatile("add.rn.f32x2 %0, %1, %2;" : "=l"(axy) : "l"(a0xy), "l"(a1xy));
    float ax, ay;
    asm volatile("mov.b64 {%0, %1}, %2;" : "=f"(ax), "=f"(ay) : "l"(axy));
    float az = a0z + a1z;

    part[q * ROWS + row] = make_float4(ax, ay, az, 0.f);
}

// ---------------- combine layer1 partials, relu, v2 = dinv * (h @ W2) ----------------
__global__ void v2_kernel(const float* __restrict__ W2, const float* __restrict__ b1)
{
    int id = blockIdx.x * blockDim.x + threadIdx.x;
    if (id >= ROWS) return;
    float4 p0 = g_pa[id];
    float4 p1 = g_pa[ROWS + id];
    float4 p2 = g_pa[2 * ROWS + id];
    float4 p3 = g_pa[3 * ROWS + id];
    float d = g_dinv[id];
    float h0 = fmaxf(d * ((p0.x + p1.x) + (p2.x + p3.x)) + b1[0], 0.f);
    float h1 = fmaxf(d * ((p0.y + p1.y) + (p2.y + p3.y)) + b1[1], 0.f);
    float h2 = fmaxf(d * ((p0.z + p1.z) + (p2.z + p3.z)) + b1[2], 0.f);
    float u0 = h0*W2[0] + h1*W2[3] + h2*W2[6];
    float u1 = h0*W2[1] + h1*W2[4] + h2*W2[7];
    float u2 = h0*W2[2] + h1*W2[5] + h2*W2[8];
    g_v2[id] = make_float4(d*u0, d*u1, d*u2, 0.f);
}

// ---------------- fc1 split-K, z built on the fly, atomic accumulate ----------------
__global__ void __launch_bounds__(128) fc1_kernel(
    const float* __restrict__ idxin, const float* __restrict__ y,
    const float* __restrict__ b2, const float* __restrict__ fcW1)
{
    __shared__ float zc[CK];
    int bx = blockIdx.x;
    int b  = bx >> 5;
    int s  = bx & 31;
    int k0 = s * CK;
    int klen = min(CK, INDIM - k0);
    int t = threadIdx.x;

    for (int kk = t; kk < klen; kk += 128) {
        int k = k0 + kk;
        float z;
        if (k < NN) {
            z = idxin[b * NN + k];
        } else if (k < NN + 3 * NN) {
            int g = k - NN;
            int i = g / 3;
            int f = g - i * 3;
            const float* p0 = (const float*)&g_pb[b * NN + i];
            const float* p1 = (const float*)&g_pb[ROWS + b * NN + i];
            const float* p2 = (const float*)&g_pb[2 * ROWS + b * NN + i];
            const float* p3 = (const float*)&g_pb[3 * ROWS + b * NN + i];
            z = g_dinv[b * NN + i] * ((p0[f] + p1[f]) + (p2[f] + p3[f])) + b2[f];
        } else {
            z = y[b * 36 + (k - (NN + 3 * NN))];
        }
        zc[kk] = z;
    }
    __syncthreads();

    float acc = 0.f;
    const float* wcol = fcW1 + (size_t)k0 * HID + t;
    int kk = 0;
    for (; kk + 4 <= klen; kk += 4) {
        acc += zc[kk+0] * wcol[(size_t)(kk+0) * HID];
        acc += zc[kk+1] * wcol[(size_t)(kk+1) * HID];
        acc += zc[kk+2] * wcol[(size_t)(kk+2) * HID];
        acc += zc[kk+3] * wcol[(size_t)(kk+3) * HID];
    }
    for (; kk < klen; ++kk)
        acc += zc[kk] * wcol[(size_t)kk * HID];

    atomicAdd(&g_zacc[b * HID + t], acc);
}

// ---------------- relu + fc2 ----------------
__global__ void __launch_bounds__(128) fin_kernel(
    const float* __restrict__ fcW2, const float* __restrict__ fcb2, float* __restrict__ out)
{
    __shared__ float sm[HID];
    int b = blockIdx.x, t = threadIdx.x;
    sm[t] = fmaxf(g_zacc[b * HID + t], 0.f);
    __syncthreads();
    if (t < NACT) {
        float o = fcb2[t];
#pragma unroll 8
        for (int h = 0; h < HID; ++h)
            o += sm[h] * fcW2[h * NACT + t];
        out[b * NACT + t] = o;
    }
}

// ---------------- launch ----------------
extern "C" void kernel_launch(void* const* d_in, const int* in_sizes, int n_in,
                              void* d_out, int out_size)
{
    const float* idxin = (const float*)d_in[0];   // [8,4096]
    const float* x     = (const float*)d_in[1];   // [8,4096,3]
    const float* y     = (const float*)d_in[2];   // [8,12,3]
    const int*   adj   = (const int*)  d_in[3];   // [8,4096,4096]
    const float* W1    = (const float*)d_in[4];
    const float* b1    = (const float*)d_in[5];
    const float* W2    = (const float*)d_in[6];
    const float* b2    = (const float*)d_in[7];
    const float* fcW1  = (const float*)d_in[8];
    const float* fcb1  = (const float*)d_in[9];
    const float* fcW2  = (const float*)d_in[10];
    const float* fcb2  = (const float*)d_in[11];
    float* out = (float*)d_out;

    prep_kernel<<<ROWS, 256>>>(adj, x, W1, fcb1);
    agg_kernel<0><<<1024, 128>>>();
    v2_kernel<<<ROWS / 256, 256>>>(W2, b1);
    agg_kernel<1><<<1024, 128>>>();
    fc1_kernel<<<BB * 32, 128>>>(idxin, y, b2, fcW1);
    fin_kernel<<<BB, 128>>>(fcW2, fcb2, out);
}